// round 10
// baseline (speedup 1.0000x reference)
#include <cuda_runtime.h>
#include <cuda_fp16.h>
#include <cstdint>

#define OMEGA0 30.0f
#define BLK 128
#define MAXCTAS 592   // 148 SMs x 4 CTAs

// ---------------- helpers ----------------
__device__ __forceinline__ float fast_sigmoid(float t) {
    return __fdividef(1.0f, 1.0f + __expf(-t));
}
__device__ __forceinline__ uint32_t pack_f16x2(float x, float y) {
    uint32_t r;
    asm("cvt.rn.f16x2.f32 %0, %1, %2;" : "=r"(r) : "f"(y), "f"(x));
    return r;
}
// D += A * B
__device__ __forceinline__ void mma_f16(float d[4], const uint32_t a[4],
                                        uint32_t b0, uint32_t b1) {
    asm volatile(
        "mma.sync.aligned.m16n8k16.row.col.f32.f16.f16.f32 "
        "{%0,%1,%2,%3}, {%4,%5,%6,%7}, {%8,%9}, {%0,%1,%2,%3};"
        : "+f"(d[0]), "+f"(d[1]), "+f"(d[2]), "+f"(d[3])
        : "r"(a[0]), "r"(a[1]), "r"(a[2]), "r"(a[3]), "r"(b0), "r"(b1));
}
// D = A * B + {c0,c1,c0,c1}
__device__ __forceinline__ void mma_f16_bias(float d[4], const uint32_t a[4],
                                             uint32_t b0, uint32_t b1,
                                             float c0, float c1) {
    asm volatile(
        "mma.sync.aligned.m16n8k16.row.col.f32.f16.f16.f32 "
        "{%0,%1,%2,%3}, {%4,%5,%6,%7}, {%8,%9}, {%10,%11,%10,%11};"
        : "=f"(d[0]), "=f"(d[1]), "=f"(d[2]), "=f"(d[3])
        : "r"(a[0]), "r"(a[1]), "r"(a[2]), "r"(a[3]), "r"(b0), "r"(b1),
          "f"(c0), "f"(c1));
}

// Build A fragments (f16) for one m-tile from its 4 n-tiles (D layout)
#define BUILD_A1(vm, Ah) do {                                   \
    Ah[0][0] = pack_f16x2((vm)[0][0], (vm)[0][1]);              \
    Ah[0][1] = pack_f16x2((vm)[0][2], (vm)[0][3]);              \
    Ah[0][2] = pack_f16x2((vm)[1][0], (vm)[1][1]);              \
    Ah[0][3] = pack_f16x2((vm)[1][2], (vm)[1][3]);              \
    Ah[1][0] = pack_f16x2((vm)[2][0], (vm)[2][1]);              \
    Ah[1][1] = pack_f16x2((vm)[2][2], (vm)[2][3]);              \
    Ah[1][2] = pack_f16x2((vm)[3][0], (vm)[3][1]);              \
    Ah[1][3] = pack_f16x2((vm)[3][2], (vm)[3][3]);              \
} while (0)

__global__ void __launch_bounds__(BLK, 4)
siren_hmma(const float* __restrict__ coords,
           const float* __restrict__ w0g, const float* __restrict__ b0g,
           const float* __restrict__ w1g, const float* __restrict__ b1g,
           const float* __restrict__ w2g, const float* __restrict__ b2g,
           const float* __restrict__ w3g, const float* __restrict__ b3g,
           const float* __restrict__ w4g, const float* __restrict__ b4g,
           const float* __restrict__ w5g, const float* __restrict__ b5g,
           const float* __restrict__ wfg, const float* __restrict__ bfg,
           float* __restrict__ out, int numPts, int numTiles)
{
    __shared__ __align__(16) uint32_t fragMid[4][32][20];
    __shared__ __align__(16) uint32_t frag5[32][12];
    __shared__ float2 biasM[4][16];
    __shared__ float2 bias5[8];
    __shared__ float s_w0[64], s_b0[32], s_wf[48], s_bf[3];

    const int tid = threadIdx.x;
    const int lane = tid & 31, wid = tid >> 5;
    const int t4 = lane & 3, g = lane >> 2;

    // ---- fill weight fragments ----
#define FILL_MID(Lc, WP)                                                       \
    for (int e = tid; e < 512; e += BLK) {                                     \
        int q = e >> 5, ln = e & 31;                                           \
        int tt = ln & 3, gg = ln >> 2;                                         \
        int kt = q >> 3, r = (q >> 2) & 1, nt = q & 3;                         \
        int k0 = kt * 16 + r * 8 + tt * 2;                                     \
        int n  = nt * 8 + gg;                                                  \
        fragMid[Lc][ln][q] = pack_f16x2(OMEGA0 * WP[n * 32 + k0],              \
                                        OMEGA0 * WP[n * 32 + k0 + 1]);         \
    }
    FILL_MID(0, w1g) FILL_MID(1, w2g) FILL_MID(2, w3g) FILL_MID(3, w4g)
#undef FILL_MID

    for (int e = tid; e < 256; e += BLK) {
        int q = e >> 5, ln = e & 31;
        int tt = ln & 3, gg = ln >> 2;
        int kt = q >> 2, r = (q >> 1) & 1, nt = q & 1;
        int k0 = kt * 16 + r * 8 + tt * 2;
        int n  = nt * 8 + gg;
        frag5[ln][q] = pack_f16x2(OMEGA0 * w5g[n * 32 + k0],
                                  OMEGA0 * w5g[n * 32 + k0 + 1]);
    }
#define FILL_BIAS(Lc, BP)                                                      \
    if (tid < 16) {                                                            \
        int nt = tid >> 2, tt = tid & 3;                                       \
        biasM[Lc][tid] = make_float2(OMEGA0 * BP[nt * 8 + tt * 2],             \
                                     OMEGA0 * BP[nt * 8 + tt * 2 + 1]);        \
    }
    FILL_BIAS(0, b1g) FILL_BIAS(1, b2g) FILL_BIAS(2, b3g) FILL_BIAS(3, b4g)
#undef FILL_BIAS
    if (tid < 8) {
        int nt = tid >> 2, tt = tid & 3;
        bias5[tid] = make_float2(OMEGA0 * b5g[nt * 8 + tt * 2],
                                 OMEGA0 * b5g[nt * 8 + tt * 2 + 1]);
    }
    if (tid < 64) s_w0[tid] = OMEGA0 * w0g[tid];
    if (tid < 32) s_b0[tid] = OMEGA0 * b0g[tid];
    if (tid < 48) s_wf[tid] = wfg[tid];
    if (tid < 3)  s_bf[tid] = bfg[tid];
    __syncthreads();

    // ---------------- main loop: 256 points per CTA-iter (64 per warp, mt=4) ----------------
#pragma unroll 1
    for (int tile = blockIdx.x; tile < numTiles; tile += gridDim.x) {
        const int pbase = tile * 256 + wid * 64;

        float v[4][4][4];   // 4 m-tiles x 4 n-tiles x 4 vals

        // ---- layer 0: 2 -> 32 ----
#pragma unroll
        for (int mt = 0; mt < 4; mt++) {
            int p0 = pbase + mt * 16 + g;
            float2 c0 = (p0 < numPts)     ? ((const float2*)coords)[p0]     : make_float2(0.f, 0.f);
            float2 c1 = (p0 + 8 < numPts) ? ((const float2*)coords)[p0 + 8] : make_float2(0.f, 0.f);
#pragma unroll
            for (int nt = 0; nt < 4; nt++) {
                int col = nt * 8 + t4 * 2;
                float2 wa = ((const float2*)s_w0)[col];
                float2 wb = ((const float2*)s_w0)[col + 1];
                float ba = s_b0[col], bb_ = s_b0[col + 1];
                v[mt][nt][0] = __sinf(fmaf(c0.x, wa.x, fmaf(c0.y, wa.y, ba)));
                v[mt][nt][1] = __sinf(fmaf(c0.x, wb.x, fmaf(c0.y, wb.y, bb_)));
                v[mt][nt][2] = __sinf(fmaf(c1.x, wa.x, fmaf(c1.y, wa.y, ba)));
                v[mt][nt][3] = __sinf(fmaf(c1.x, wb.x, fmaf(c1.y, wb.y, bb_)));
            }
        }

        // ---- 4 middle layers 32 -> 32 on HMMA ----
#pragma unroll 1
        for (int L = 0; L < 4; L++) {
            uint32_t B[16];
            {
                const uint4* bp = (const uint4*)&fragMid[L][lane][0];
                uint4 b0_ = bp[0], b1_ = bp[1], b2_ = bp[2], b3_ = bp[3];
                B[0]=b0_.x; B[1]=b0_.y; B[2]=b0_.z; B[3]=b0_.w;
                B[4]=b1_.x; B[5]=b1_.y; B[6]=b1_.z; B[7]=b1_.w;
                B[8]=b2_.x; B[9]=b2_.y; B[10]=b2_.z; B[11]=b2_.w;
                B[12]=b3_.x; B[13]=b3_.y; B[14]=b3_.z; B[15]=b3_.w;
            }
            float2 bb0 = biasM[L][t4], bb1 = biasM[L][4 + t4];
            float2 bb2 = biasM[L][8 + t4], bb3 = biasM[L][12 + t4];
#pragma unroll
            for (int mt = 0; mt < 4; mt++) {
                uint32_t Ah[2][4];
                BUILD_A1(v[mt], Ah);
                mma_f16_bias(v[mt][0], Ah[0], B[0], B[4], bb0.x, bb0.y);
                mma_f16     (v[mt][0], Ah[1], B[8], B[12]);
                mma_f16_bias(v[mt][1], Ah[0], B[1], B[5], bb1.x, bb1.y);
                mma_f16     (v[mt][1], Ah[1], B[9], B[13]);
                mma_f16_bias(v[mt][2], Ah[0], B[2], B[6], bb2.x, bb2.y);
                mma_f16     (v[mt][2], Ah[1], B[10], B[14]);
                mma_f16_bias(v[mt][3], Ah[0], B[3], B[7], bb3.x, bb3.y);
                mma_f16     (v[mt][3], Ah[1], B[11], B[15]);
            }
            // sine
#pragma unroll
            for (int mt = 0; mt < 4; mt++)
#pragma unroll
                for (int nt = 0; nt < 4; nt++)
#pragma unroll
                    for (int i = 0; i < 4; i++)
                        v[mt][nt][i] = __sinf(v[mt][nt][i]);
        }

        // ---- layer 5: 32 -> 16 on HMMA ----
        {
            uint32_t B5[8];
            {
                const uint4* bp = (const uint4*)&frag5[lane][0];
                uint4 b0_ = bp[0], b1_ = bp[1];
                B5[0]=b0_.x; B5[1]=b0_.y; B5[2]=b0_.z; B5[3]=b0_.w;
                B5[4]=b1_.x; B5[5]=b1_.y; B5[6]=b1_.z; B5[7]=b1_.w;
            }
            float2 bb0 = bias5[t4], bb1 = bias5[4 + t4];
#pragma unroll
            for (int mt = 0; mt < 4; mt++) {
                uint32_t Ah[2][4];
                BUILD_A1(v[mt], Ah);
                mma_f16_bias(v[mt][0], Ah[0], B5[0], B5[2], bb0.x, bb0.y);
                mma_f16     (v[mt][0], Ah[1], B5[4], B5[6]);
                mma_f16_bias(v[mt][1], Ah[0], B5[1], B5[3], bb1.x, bb1.y);
                mma_f16     (v[mt][1], Ah[1], B5[5], B5[7]);
            }
#pragma unroll
            for (int mt = 0; mt < 4; mt++)
#pragma unroll
                for (int nt = 0; nt < 2; nt++)
#pragma unroll
                    for (int i = 0; i < 4; i++)
                        v[mt][nt][i] = __sinf(v[mt][nt][i]);
        }

        // ---- final 16 -> 3 + sigmoid ----
#pragma unroll
        for (int mt = 0; mt < 4; mt++) {
            float s[2][3];
#pragma unroll
            for (int c = 0; c < 3; c++) {
                float2 wa = ((const float2*)s_wf)[c * 8 + t4];
                float2 wb = ((const float2*)s_wf)[c * 8 + 4 + t4];
#pragma unroll
                for (int r = 0; r < 2; r++) {
                    float acc = v[mt][0][2 * r]     * wa.x
                              + v[mt][0][2 * r + 1] * wa.y
                              + v[mt][1][2 * r]     * wb.x
                              + v[mt][1][2 * r + 1] * wb.y;
                    acc += __shfl_xor_sync(0xffffffffu, acc, 1);
                    acc += __shfl_xor_sync(0xffffffffu, acc, 2);
                    s[r][c] = acc + s_bf[c];
                }
            }
            if (t4 < 3) {
#pragma unroll
                for (int r = 0; r < 2; r++) {
                    int p = pbase + mt * 16 + g + 8 * r;
                    if (p < numPts) {
                        float val = (t4 == 0) ? s[r][0] : ((t4 == 1) ? s[r][1] : s[r][2]);
                        out[(size_t)p * 3 + t4] = fast_sigmoid(val);
                    }
                }
            }
        }
    }
}

extern "C" void kernel_launch(void* const* d_in, const int* in_sizes, int n_in,
                              void* d_out, int out_size)
{
    const float* coords = (const float*)d_in[0];
    const float* w0 = (const float*)d_in[1];  const float* b0 = (const float*)d_in[2];
    const float* w1 = (const float*)d_in[3];  const float* b1 = (const float*)d_in[4];
    const float* w2 = (const float*)d_in[5];  const float* b2 = (const float*)d_in[6];
    const float* w3 = (const float*)d_in[7];  const float* b3 = (const float*)d_in[8];
    const float* w4 = (const float*)d_in[9];  const float* b4 = (const float*)d_in[10];
    const float* w5 = (const float*)d_in[11]; const float* b5 = (const float*)d_in[12];
    const float* wf = (const float*)d_in[13]; const float* bf = (const float*)d_in[14];

    int numPts = in_sizes[0] / 2;
    int numTiles = (numPts + 255) / 256;
    int grid = numTiles < MAXCTAS ? numTiles : MAXCTAS;

    siren_hmma<<<grid, BLK>>>(coords, w0, b0, w1, b1, w2, b2, w3, b3, w4, b4,
                              w5, b5, wf, bf, (float*)d_out, numPts, numTiles);
}